// round 2
// baseline (speedup 1.0000x reference)
#include <cuda_runtime.h>

#define WINN 49
#define CC 128
#define C3 384
#define QS_STRIDE 388   // pad to reduce smem bank conflicts on row-strided access
#define NHEAD 4
#define HD 32

constexpr int XS_F = WINN * CC;            // 6272 floats  (x, later attn_out)
constexpr int QS_F = WINN * QS_STRIDE;     // 19012 floats (qkv)
constexpr int WT_F = 128 * 128;            // 16384 floats (W tile / scores / proj_w)
constexpr int SMEM_BYTES = (XS_F + QS_F + WT_F) * 4;  // 166,672 B

__global__ void __launch_bounds__(384, 1)
swin_fused(const float* __restrict__ x, const float* __restrict__ mask,
           const float* __restrict__ qkv_w, const float* __restrict__ qkv_b,
           const float* __restrict__ proj_w, const float* __restrict__ proj_b,
           const float* __restrict__ rel_table, float* __restrict__ out)
{
    extern __shared__ float sm[];
    float* xs = sm;                   // x window, later attn_out
    float* qs = sm + XS_F;            // qkv [49][388]: q @+0, k @+128, v @+256
    float* wt = sm + XS_F + QS_F;     // weight tile / scores[4][49][49] / proj_w

    const int bw  = blockIdx.x;       // 0..2047
    const int tid = threadIdx.x;      // 0..383
    const int wi  = bw & 63;          // mask window index (nW=64 inner dim)

    // ---------------- Phase 1: load x window (49x128) ----------------
    {
        const float4* xg = reinterpret_cast<const float4*>(x) + (size_t)bw * (XS_F / 4);
        float4* xd = reinterpret_cast<float4*>(xs);
        for (int i = tid; i < XS_F / 4; i += 384) xd[i] = xg[i];
    }

    const int jl    = tid & 31;               // j-lane: columns jl*4..jl*4+3
    const int grp   = tid >> 5;               // row group 0..11
    const int nrows = (grp == 0) ? 5 : 4;     // rows n = grp + 12*r

    // ---------------- Phase 2: QKV GEMM (49x384 = x @ qkv_w + b) ----------------
    for (int jt = 0; jt < 3; jt++) {
        __syncthreads();                      // wt free (prev compute / phase1 done)
        const int j0 = jt * 128;
        {
            const float4* wg = reinterpret_cast<const float4*>(qkv_w);
            float4* wd = reinterpret_cast<float4*>(wt);
            for (int i = tid; i < 128 * 32; i += 384) {
                const int k = i >> 5, j4 = i & 31;
                wd[k * 32 + j4] = wg[k * 96 + (j0 >> 2) + j4];
            }
        }
        __syncthreads();

        float acc[5][4];
        #pragma unroll
        for (int r = 0; r < 5; r++) { acc[r][0]=0.f; acc[r][1]=0.f; acc[r][2]=0.f; acc[r][3]=0.f; }

        #pragma unroll 4
        for (int k = 0; k < 128; k++) {
            const float4 w4 = *reinterpret_cast<const float4*>(&wt[k * 128 + jl * 4]);
            #pragma unroll
            for (int r = 0; r < 5; r++) {
                if (r < nrows) {                       // warp-uniform predicate
                    const float xv = xs[(grp + 12 * r) * CC + k];
                    acc[r][0] += xv * w4.x; acc[r][1] += xv * w4.y;
                    acc[r][2] += xv * w4.z; acc[r][3] += xv * w4.w;
                }
            }
        }
        const float4 b4 = *reinterpret_cast<const float4*>(&qkv_b[j0 + jl * 4]);
        #pragma unroll
        for (int r = 0; r < 5; r++) {
            if (r < nrows) {
                const int n = grp + 12 * r;
                float4 o;
                o.x = acc[r][0] + b4.x; o.y = acc[r][1] + b4.y;
                o.z = acc[r][2] + b4.z; o.w = acc[r][3] + b4.w;
                *reinterpret_cast<float4*>(&qs[n * QS_STRIDE + j0 + jl * 4]) = o;
            }
        }
    }
    __syncthreads();   // qkv complete; wt free for scores

    // ---------------- Phase 3: scores S[h][i][j] = scale*q.k + bias + mask ----------------
    // 196 rows x 2 halves = 392 work items on 384 threads -> strided loop (fixes
    // the missing rows 192..195 coverage bug from R1).
    for (int w = tid; w < 2 * NHEAD * WINN; w += 384) {
        const int pr   = w >> 1;      // (h,i) pair, 0..195
        const int half = w & 1;       // split j space
        const int h = pr / WINN;
        const int i = pr - h * WINN;
        const float* qrow = qs + i * QS_STRIDE + h * HD;
        float qv[HD];
        #pragma unroll
        for (int d = 0; d < HD; d++) qv[d] = qrow[d] * 0.17677669529663687f; // 1/sqrt(32)
        const int qr = i / 7, qc = i - qr * 7;
        for (int j = half; j < WINN; j += 2) {
            const float* krow = qs + j * QS_STRIDE + 128 + h * HD;
            float s = 0.f;
            #pragma unroll
            for (int d = 0; d < HD; d++) s += qv[d] * krow[d];
            const int kr = j / 7, kc = j - kr * 7;
            const int ridx = (qr - kr + 6) * 13 + (qc - kc + 6);
            s += rel_table[ridx * NHEAD + h];
            s += mask[wi * (WINN * WINN) + i * WINN + j];
            wt[h * (WINN * WINN) + i * WINN + j] = s;
        }
    }
    __syncthreads();

    // ---------------- Phase 3b: softmax over j (one thread per (h,i) row) ----------------
    if (tid < NHEAD * WINN) {
        const int h = tid / WINN;
        const int i = tid - h * WINN;
        float* row = wt + h * (WINN * WINN) + i * WINN;
        float p[WINN];
        float m = -1e30f;
        #pragma unroll
        for (int j = 0; j < WINN; j++) { p[j] = row[j]; m = fmaxf(m, p[j]); }
        float ssum = 0.f;
        #pragma unroll
        for (int j = 0; j < WINN; j++) { p[j] = __expf(p[j] - m); ssum += p[j]; }
        const float inv = 1.0f / ssum;
        #pragma unroll
        for (int j = 0; j < WINN; j++) row[j] = p[j] * inv;
    }
    __syncthreads();

    // ---------------- Phase 4: attn_out = P @ V  (into xs) ----------------
    {
        const int h   = tid / 96;
        const int t96 = tid - h * 96;
        const int d   = t96 & 31;
        const int g3  = t96 >> 5;                 // 0..2, rows i = g3 + 3*r
        const int nr  = (g3 == 0) ? 17 : 16;
        float acc[17];
        #pragma unroll
        for (int r = 0; r < 17; r++) acc[r] = 0.f;
        for (int j = 0; j < WINN; j++) {
            const float vv = qs[j * QS_STRIDE + 256 + h * HD + d];
            const float* prow = wt + h * (WINN * WINN) + j;
            #pragma unroll
            for (int r = 0; r < 17; r++)
                if (r < nr) acc[r] += prow[(g3 + 3 * r) * WINN] * vv;
        }
        #pragma unroll
        for (int r = 0; r < 17; r++)
            if (r < nr) xs[(g3 + 3 * r) * CC + h * HD + d] = acc[r];
    }
    __syncthreads();   // P no longer needed; wt free for proj_w

    // ---------------- Phase 5: proj GEMM (out = attn_out @ proj_w + b) ----------------
    {
        const float4* wg = reinterpret_cast<const float4*>(proj_w);
        float4* wd = reinterpret_cast<float4*>(wt);
        for (int i = tid; i < 128 * 32; i += 384) wd[i] = wg[i];
    }
    __syncthreads();
    {
        float acc[5][4];
        #pragma unroll
        for (int r = 0; r < 5; r++) { acc[r][0]=0.f; acc[r][1]=0.f; acc[r][2]=0.f; acc[r][3]=0.f; }
        #pragma unroll 4
        for (int k = 0; k < 128; k++) {
            const float4 w4 = *reinterpret_cast<const float4*>(&wt[k * 128 + jl * 4]);
            #pragma unroll
            for (int r = 0; r < 5; r++) {
                if (r < nrows) {
                    const float xv = xs[(grp + 12 * r) * CC + k];
                    acc[r][0] += xv * w4.x; acc[r][1] += xv * w4.y;
                    acc[r][2] += xv * w4.z; acc[r][3] += xv * w4.w;
                }
            }
        }
        const float4 b4 = *reinterpret_cast<const float4*>(&proj_b[jl * 4]);
        float4* og = reinterpret_cast<float4*>(out) + (size_t)bw * (XS_F / 4);
        #pragma unroll
        for (int r = 0; r < 5; r++) {
            if (r < nrows) {
                const int n = grp + 12 * r;
                float4 o;
                o.x = acc[r][0] + b4.x; o.y = acc[r][1] + b4.y;
                o.z = acc[r][2] + b4.z; o.w = acc[r][3] + b4.w;
                og[n * 32 + jl] = o;
            }
        }
    }
}

extern "C" void kernel_launch(void* const* d_in, const int* in_sizes, int n_in,
                              void* d_out, int out_size)
{
    const float* x      = (const float*)d_in[0];
    const float* mask   = (const float*)d_in[1];
    const float* qkv_w  = (const float*)d_in[2];
    const float* qkv_b  = (const float*)d_in[3];
    const float* proj_w = (const float*)d_in[4];
    const float* proj_b = (const float*)d_in[5];
    const float* rel    = (const float*)d_in[6];
    float* out = (float*)d_out;

    // Idempotent, capture-safe (not a stream op); called every launch per determinism rules.
    cudaFuncSetAttribute(swin_fused, cudaFuncAttributeMaxDynamicSharedMemorySize, SMEM_BYTES);

    swin_fused<<<2048, 384, SMEM_BYTES>>>(x, mask, qkv_w, qkv_b, proj_w, proj_b, rel, out);
}

// round 3
// speedup vs baseline: 1.1497x; 1.1497x over previous
#include <cuda_runtime.h>

#define WINN 49
#define CC 128
#define QS_STRIDE 388   // multiple of 4 (16B-aligned rows), ==4 mod 32 banks
#define NHEAD 4
#define HD 32
#define SROW 52         // score row stride (pad 49 -> 52 for float4 alignment)
#define SH (WINN * SROW)  // 2548 per head

constexpr int XS_F = WINN * CC;            // 6272 floats  (x -> mask -> attn_out)
constexpr int QS_F = WINN * QS_STRIDE;     // 19012 floats (qkv)
constexpr int WT_F = 128 * 128;            // 16384 floats (W tile / scores / proj_w)
constexpr int SMEM_BYTES = (XS_F + QS_F + WT_F) * 4;  // 166,672 B

// ---------------- packed f32x2 helpers ----------------
__device__ __forceinline__ unsigned long long pack2(float x) {
    unsigned long long r;
    asm("mov.b64 %0, {%1, %1};" : "=l"(r) : "f"(x));
    return r;
}
__device__ __forceinline__ void fma2(unsigned long long& a, unsigned long long x, unsigned long long w) {
    asm("fma.rn.f32x2 %0, %1, %2, %0;" : "+l"(a) : "l"(x), "l"(w));
}
__device__ __forceinline__ float2 unpack2(unsigned long long v) {
    float2 f;
    asm("mov.b64 {%0, %1}, %2;" : "=f"(f.x), "=f"(f.y) : "l"(v));
    return f;
}

// 49x128 GEMM tile: acc[r] (packed 2 cols) = xs[49x128] @ wt[128x128] for
// rows n = grp6 + 6*r, cols cg*64 + jl*2 .. +1.  nr is warp-uniform.
__device__ __forceinline__ void gemm_49x128(const float* __restrict__ xsrc,
                                            const float* __restrict__ wt,
                                            int grp6, int cg, int jl, int nr,
                                            unsigned long long acc[9])
{
    #pragma unroll
    for (int r = 0; r < 9; r++) acc[r] = 0ull;
    const float* wcol = wt + cg * 64 + jl * 2;
    #pragma unroll 2
    for (int k0 = 0; k0 < 128; k0 += 4) {
        float4 xr[9];
        #pragma unroll
        for (int r = 0; r < 9; r++)
            if (r < nr) xr[r] = *reinterpret_cast<const float4*>(&xsrc[(grp6 + 6 * r) * CC + k0]);
        #pragma unroll
        for (int kk = 0; kk < 4; kk++) {
            const unsigned long long w64 =
                *reinterpret_cast<const unsigned long long*>(&wcol[(k0 + kk) * 128]);
            #pragma unroll
            for (int r = 0; r < 9; r++)
                if (r < nr) {
                    const float xv = (kk == 0) ? xr[r].x : (kk == 1) ? xr[r].y
                                   : (kk == 2) ? xr[r].z : xr[r].w;
                    fma2(acc[r], pack2(xv), w64);
                }
        }
    }
}

__global__ void __launch_bounds__(384, 1)
swin_fused(const float* __restrict__ x, const float* __restrict__ mask,
           const float* __restrict__ qkv_w, const float* __restrict__ qkv_b,
           const float* __restrict__ proj_w, const float* __restrict__ proj_b,
           const float* __restrict__ rel_table, float* __restrict__ out)
{
    extern __shared__ float sm[];
    float* xs = sm;                   // x window -> mask -> attn_out
    float* qs = sm + XS_F;            // qkv [49][388]: q @+0, k @+128, v @+256
    float* wt = sm + XS_F + QS_F;     // weight tile / scores[4][49][52] / proj_w

    const int bw  = blockIdx.x;       // 0..2047
    const int tid = threadIdx.x;      // 0..383
    const int wi  = bw & 63;          // mask window index (nW=64 inner dim)

    // ---------------- Phase 1: load x window (49x128) ----------------
    {
        const float4* xg = reinterpret_cast<const float4*>(x) + (size_t)bw * (XS_F / 4);
        float4* xd = reinterpret_cast<float4*>(xs);
        for (int i = tid; i < XS_F / 4; i += 384) xd[i] = xg[i];
    }

    const int warp = tid >> 5;
    const int jl   = tid & 31;
    const int grp6 = warp >> 1;               // 0..5 row group
    const int cg   = warp & 1;                // 0..1 column group (64 cols)
    const int nr   = (grp6 == 0) ? 9 : 8;     // rows n = grp6 + 6*r

    // ---------------- Phase 2: QKV GEMM (49x384 = x @ qkv_w + b) ----------------
    for (int jt = 0; jt < 3; jt++) {
        __syncthreads();                      // wt free (prev gemm / phase1 done)
        const int j0 = jt * 128;
        {
            const float4* wg = reinterpret_cast<const float4*>(qkv_w);
            float4* wd = reinterpret_cast<float4*>(wt);
            for (int i = tid; i < 128 * 32; i += 384) {
                const int k = i >> 5, j4 = i & 31;
                wd[k * 32 + j4] = wg[k * 96 + (j0 >> 2) + j4];
            }
        }
        __syncthreads();

        unsigned long long acc[9];
        gemm_49x128(xs, wt, grp6, cg, jl, nr, acc);

        const float2 b2 = *reinterpret_cast<const float2*>(&qkv_b[j0 + cg * 64 + jl * 2]);
        #pragma unroll
        for (int r = 0; r < 9; r++)
            if (r < nr) {
                const int n = grp6 + 6 * r;
                float2 a = unpack2(acc[r]);
                a.x += b2.x; a.y += b2.y;
                *reinterpret_cast<float2*>(&qs[n * QS_STRIDE + j0 + cg * 64 + jl * 2]) = a;
            }
    }
    __syncthreads();   // qkv complete; xs (x) dead; wt free for scores

    // ---------------- Phase 2b: stage mask window into xs ----------------
    {
        const float* mw = mask + (size_t)wi * (WINN * WINN);
        for (int i = tid; i < WINN * WINN; i += 384) xs[i] = mw[i];
    }
    __syncthreads();

    // ---------------- Phase 3: scores S[h][i][j] = scale*q.k + bias + mask ----------------
    for (int w = tid; w < 2 * NHEAD * WINN; w += 384) {
        const int pr   = w >> 1;      // (h,i), 0..195
        const int half = w & 1;
        const int h = pr / WINN;
        const int i = pr - h * WINN;
        const float* qrow = qs + i * QS_STRIDE + h * HD;
        unsigned long long qd[16];
        #pragma unroll
        for (int p = 0; p < 8; p++) {
            const ulonglong2 t = *reinterpret_cast<const ulonglong2*>(&qrow[p * 4]);
            qd[2 * p] = t.x; qd[2 * p + 1] = t.y;
        }
        const int qr = i / 7, qc = i - qr * 7;
        for (int j = half; j < WINN; j += 2) {
            const float* krow = qs + j * QS_STRIDE + 128 + h * HD;
            unsigned long long a0 = 0ull, a1 = 0ull;
            #pragma unroll
            for (int p = 0; p < 8; p++) {
                const ulonglong2 kv = *reinterpret_cast<const ulonglong2*>(&krow[p * 4]);
                fma2(a0, qd[2 * p], kv.x);
                fma2(a1, qd[2 * p + 1], kv.y);
            }
            const float2 f0 = unpack2(a0), f1 = unpack2(a1);
            float s = (f0.x + f0.y + f1.x + f1.y) * 0.17677669529663687f; // 1/sqrt(32)
            const int kr = j / 7, kc = j - kr * 7;
            const int ridx = (qr - kr + 6) * 13 + (qc - kc + 6);
            s += rel_table[ridx * NHEAD + h];
            s += xs[i * WINN + j];
            wt[h * SH + i * SROW + j] = s;
        }
    }
    __syncthreads();

    // ---------------- Phase 3b: softmax over j (one thread per (h,i) row) ----------------
    if (tid < NHEAD * WINN) {
        const int h = tid / WINN;
        const int i = tid - h * WINN;
        float* row = wt + h * SH + i * SROW;
        float p[WINN];
        float m = -1e30f;
        #pragma unroll
        for (int j = 0; j < WINN; j++) { p[j] = row[j]; m = fmaxf(m, p[j]); }
        float ssum = 0.f;
        #pragma unroll
        for (int j = 0; j < WINN; j++) { p[j] = __expf(p[j] - m); ssum += p[j]; }
        const float inv = 1.0f / ssum;
        #pragma unroll
        for (int j = 0; j < WINN; j++) row[j] = p[j] * inv;
    }
    __syncthreads();

    // ---------------- Phase 4: attn_out = P @ V  (into xs) ----------------
    {
        const int h   = tid / 96;
        const int t96 = tid - h * 96;
        const int d   = t96 & 31;
        const int g3  = t96 >> 5;                 // rows i = g3 + 3*r
        const int nrv = (g3 == 0) ? 17 : 16;
        const float* vbase = qs + 256 + h * HD + d;
        const float* pbase = wt + h * SH + g3 * SROW;
        float acc[17];
        #pragma unroll
        for (int r = 0; r < 17; r++) acc[r] = 0.f;
        for (int j0 = 0; j0 < 48; j0 += 4) {
            const float v0 = vbase[(j0 + 0) * QS_STRIDE];
            const float v1 = vbase[(j0 + 1) * QS_STRIDE];
            const float v2 = vbase[(j0 + 2) * QS_STRIDE];
            const float v3 = vbase[(j0 + 3) * QS_STRIDE];
            #pragma unroll
            for (int r = 0; r < 17; r++)
                if (r < nrv) {
                    const float4 p4 = *reinterpret_cast<const float4*>(&pbase[r * 3 * SROW + j0]);
                    acc[r] += p4.x * v0 + p4.y * v1 + p4.z * v2 + p4.w * v3;
                }
        }
        {
            const float v48 = vbase[48 * QS_STRIDE];
            #pragma unroll
            for (int r = 0; r < 17; r++)
                if (r < nrv) acc[r] += pbase[r * 3 * SROW + 48] * v48;
        }
        #pragma unroll
        for (int r = 0; r < 17; r++)
            if (r < nrv) xs[(g3 + 3 * r) * CC + h * HD + d] = acc[r];
    }
    __syncthreads();   // P dead; wt free for proj_w; xs = attn_out

    // ---------------- Phase 5: proj GEMM (out = attn_out @ proj_w + b) ----------------
    {
        const float4* wg = reinterpret_cast<const float4*>(proj_w);
        float4* wd = reinterpret_cast<float4*>(wt);
        for (int i = tid; i < 128 * 32; i += 384) wd[i] = wg[i];
    }
    __syncthreads();
    {
        unsigned long long acc[9];
        gemm_49x128(xs, wt, grp6, cg, jl, nr, acc);

        const float2 b2 = *reinterpret_cast<const float2*>(&proj_b[cg * 64 + jl * 2]);
        float* og = out + (size_t)bw * XS_F;
        #pragma unroll
        for (int r = 0; r < 9; r++)
            if (r < nr) {
                const int n = grp6 + 6 * r;
                float2 a = unpack2(acc[r]);
                a.x += b2.x; a.y += b2.y;
                *reinterpret_cast<float2*>(&og[n * CC + cg * 64 + jl * 2]) = a;
            }
    }
}

extern "C" void kernel_launch(void* const* d_in, const int* in_sizes, int n_in,
                              void* d_out, int out_size)
{
    const float* x      = (const float*)d_in[0];
    const float* mask   = (const float*)d_in[1];
    const float* qkv_w  = (const float*)d_in[2];
    const float* qkv_b  = (const float*)d_in[3];
    const float* proj_w = (const float*)d_in[4];
    const float* proj_b = (const float*)d_in[5];
    const float* rel    = (const float*)d_in[6];
    float* out = (float*)d_out;

    cudaFuncSetAttribute(swin_fused, cudaFuncAttributeMaxDynamicSharedMemorySize, SMEM_BYTES);

    swin_fused<<<2048, 384, SMEM_BYTES>>>(x, mask, qkv_w, qkv_b, proj_w, proj_b, rel, out);
}